// round 7
// baseline (speedup 1.0000x reference)
#include <cuda_runtime.h>
#include <cstdint>

constexpr int Bc = 32;
constexpr int Hc = 512;
constexpr int Wc = 512;
constexpr int Pc = 100000;
constexpr long long Nc = (long long)Bc * Pc;   // 3,200,000 points
constexpr int BDIM = 256;
constexpr int PPT  = 4;                        // points per thread
constexpr int NBLK = (int)(Nc / ((long long)BDIM * PPT));  // 3125 blocks
static_assert(Nc % ((long long)BDIM * PPT) == 0, "grid must tile exactly");
static_assert(Pc % PPT == 0, "4 consecutive points always share a batch index");

__device__ float g_sum = 0.0f;   // reset by epilogue every launch

__device__ __forceinline__ float point_loss(float zA, float zB, int o) {
    float d  = zA - zB;
    float gt = (float)o - 1.0f;          // in {-1, 0, +1}
    float sm = log1pf(expf(-gt * d));    // soft-margin branch (gt = +/-1)
    return (o == 1) ? (d * d) : sm;
}

__device__ __forceinline__ int4 ldcs4(const int* p) {
    return __ldcs(reinterpret_cast<const int4*>(p));
}

__global__ __launch_bounds__(BDIM)
void loss_kernel(const float* __restrict__ img,
                 const int* __restrict__ xA,
                 const int* __restrict__ yA,
                 const int* __restrict__ xB,
                 const int* __restrict__ yB,
                 const int* __restrict__ ord)
{
    const long long base = ((long long)blockIdx.x * BDIM + threadIdx.x) * PPT;

    // 4 consecutive points: same batch (P % 4 == 0, base % 4 == 0)
    const int b = (int)(base / Pc);
    const float* __restrict__ imgb = img + (long long)b * (Hc * Wc);

    // 128-bit evict-first streaming loads of all five int32 streams
    // (keeps the 33.5MB image resident in L2 across graph replays)
    int4 xa = ldcs4(xA + base);
    int4 ya = ldcs4(yA + base);
    int4 xb = ldcs4(xB + base);
    int4 yb = ldcs4(yB + base);
    int4 o4 = ldcs4(ord + base);

    // Offsets: y*512 + x
    unsigned offA0 = ((unsigned)ya.x << 9) | (unsigned)xa.x;
    unsigned offA1 = ((unsigned)ya.y << 9) | (unsigned)xa.y;
    unsigned offA2 = ((unsigned)ya.z << 9) | (unsigned)xa.z;
    unsigned offA3 = ((unsigned)ya.w << 9) | (unsigned)xa.w;
    unsigned offB0 = ((unsigned)yb.x << 9) | (unsigned)xb.x;
    unsigned offB1 = ((unsigned)yb.y << 9) | (unsigned)xb.y;
    unsigned offB2 = ((unsigned)yb.z << 9) | (unsigned)xb.z;
    unsigned offB3 = ((unsigned)yb.w << 9) | (unsigned)xb.w;

    // Issue all 8 gathers before consuming (MLP)
    float zA0 = __ldg(imgb + offA0);
    float zA1 = __ldg(imgb + offA1);
    float zA2 = __ldg(imgb + offA2);
    float zA3 = __ldg(imgb + offA3);
    float zB0 = __ldg(imgb + offB0);
    float zB1 = __ldg(imgb + offB1);
    float zB2 = __ldg(imgb + offB2);
    float zB3 = __ldg(imgb + offB3);

    float s = point_loss(zA0, zB0, o4.x)
            + point_loss(zA1, zB1, o4.y)
            + point_loss(zA2, zB2, o4.z)
            + point_loss(zA3, zB3, o4.w);

    // Warp reduce
    #pragma unroll
    for (int off = 16; off > 0; off >>= 1)
        s += __shfl_xor_sync(0xFFFFFFFFu, s, off);

    __shared__ float warp_sums[BDIM / 32];
    int lane = threadIdx.x & 31;
    int wid  = threadIdx.x >> 5;
    if (lane == 0) warp_sums[wid] = s;
    __syncthreads();

    if (threadIdx.x == 0) {
        float v = warp_sums[0];
        #pragma unroll
        for (int w = 1; w < BDIM / 32; w++) v += warp_sums[w];
        // Fire-and-forget reduction: result unused -> RED.E.ADD.F32,
        // no return-trip latency, no fence, CTA retires immediately.
        atomicAdd(&g_sum, v);
    }
}

// PDL epilogue: launched concurrently with the loss grid; blocks at the grid
// dependency (which includes the memory flush of all RED ops), then finalizes.
__global__ void epilogue_kernel(float* __restrict__ out)
{
    cudaGridDependencySynchronize();
    if (threadIdx.x == 0) {
        out[0] = g_sum * (1.0f / (float)Nc);
        g_sum = 0.0f;              // reset for next graph replay
    }
}

extern "C" void kernel_launch(void* const* d_in, const int* in_sizes, int n_in,
                              void* d_out, int out_size)
{
    const float* img = (const float*)d_in[0];
    const int*   xA  = (const int*)d_in[1];
    const int*   yA  = (const int*)d_in[2];
    const int*   xB  = (const int*)d_in[3];
    const int*   yB  = (const int*)d_in[4];
    const int*   ord = (const int*)d_in[5];
    float* out = (float*)d_out;

    loss_kernel<<<NBLK, BDIM>>>(img, xA, yA, xB, yB, ord);

    // Epilogue with programmatic stream serialization: its launch overhead
    // overlaps the loss grid; cudaGridDependencySynchronize provides the
    // ordering + visibility.
    cudaLaunchConfig_t cfg = {};
    cfg.gridDim  = dim3(1, 1, 1);
    cfg.blockDim = dim3(32, 1, 1);
    cfg.dynamicSmemBytes = 0;
    cfg.stream = 0;  // legacy default stream (same one being captured)
    cudaLaunchAttribute attrs[1];
    attrs[0].id = cudaLaunchAttributeProgrammaticStreamSerialization;
    attrs[0].val.programmaticStreamSerializationAllowed = 1;
    cfg.attrs = attrs;
    cfg.numAttrs = 1;
    cudaLaunchKernelEx(&cfg, epilogue_kernel, out);
}

// round 8
// speedup vs baseline: 1.0385x; 1.0385x over previous
#include <cuda_runtime.h>
#include <cstdint>

constexpr int Bc = 32;
constexpr int Hc = 512;
constexpr int Wc = 512;
constexpr int Pc = 100000;
constexpr long long Nc = (long long)Bc * Pc;   // 3,200,000 points
constexpr int BDIM = 256;
constexpr int PPT  = 4;                        // points per thread
constexpr int NBLK = (int)(Nc / ((long long)BDIM * PPT));  // 3125 blocks
static_assert(Nc % ((long long)BDIM * PPT) == 0, "grid must tile exactly");
static_assert(Pc % PPT == 0, "4 consecutive points always share a batch index");

__device__ float g_zero = 0.0f;   // source for the zero-init memcpy node

__device__ __forceinline__ float point_loss(float zA, float zB, int o) {
    float d  = zA - zB;
    float gt = (float)o - 1.0f;          // in {-1, 0, +1}
    float sm = log1pf(expf(-gt * d));    // soft-margin branch (gt = +/-1)
    return (o == 1) ? (d * d) : sm;
}

__device__ __forceinline__ int4 ldcs4(const int* p) {
    return __ldcs(reinterpret_cast<const int4*>(p));
}

__global__ __launch_bounds__(BDIM)
void loss_kernel(const float* __restrict__ img,
                 const int* __restrict__ xA,
                 const int* __restrict__ yA,
                 const int* __restrict__ xB,
                 const int* __restrict__ yB,
                 const int* __restrict__ ord,
                 float* __restrict__ out)
{
    const long long base = ((long long)blockIdx.x * BDIM + threadIdx.x) * PPT;

    // 4 consecutive points: same batch (P % 4 == 0, base % 4 == 0)
    const int b = (int)(base / Pc);
    const float* __restrict__ imgb = img + (long long)b * (Hc * Wc);

    // 128-bit evict-first streaming loads of all five int32 streams
    // (keeps the 33.5MB image resident in L2 across graph replays)
    int4 xa = ldcs4(xA + base);
    int4 ya = ldcs4(yA + base);
    int4 xb = ldcs4(xB + base);
    int4 yb = ldcs4(yB + base);
    int4 o4 = ldcs4(ord + base);

    // Offsets: y*512 + x
    unsigned offA0 = ((unsigned)ya.x << 9) | (unsigned)xa.x;
    unsigned offA1 = ((unsigned)ya.y << 9) | (unsigned)xa.y;
    unsigned offA2 = ((unsigned)ya.z << 9) | (unsigned)xa.z;
    unsigned offA3 = ((unsigned)ya.w << 9) | (unsigned)xa.w;
    unsigned offB0 = ((unsigned)yb.x << 9) | (unsigned)xb.x;
    unsigned offB1 = ((unsigned)yb.y << 9) | (unsigned)xb.y;
    unsigned offB2 = ((unsigned)yb.z << 9) | (unsigned)xb.z;
    unsigned offB3 = ((unsigned)yb.w << 9) | (unsigned)xb.w;

    // Issue all 8 gathers before consuming (MLP)
    float zA0 = __ldg(imgb + offA0);
    float zA1 = __ldg(imgb + offA1);
    float zA2 = __ldg(imgb + offA2);
    float zA3 = __ldg(imgb + offA3);
    float zB0 = __ldg(imgb + offB0);
    float zB1 = __ldg(imgb + offB1);
    float zB2 = __ldg(imgb + offB2);
    float zB3 = __ldg(imgb + offB3);

    float s = point_loss(zA0, zB0, o4.x)
            + point_loss(zA1, zB1, o4.y)
            + point_loss(zA2, zB2, o4.z)
            + point_loss(zA3, zB3, o4.w);

    // Warp reduce
    #pragma unroll
    for (int off = 16; off > 0; off >>= 1)
        s += __shfl_xor_sync(0xFFFFFFFFu, s, off);

    __shared__ float warp_sums[BDIM / 32];
    int lane = threadIdx.x & 31;
    int wid  = threadIdx.x >> 5;
    if (lane == 0) warp_sums[wid] = s;
    __syncthreads();

    if (threadIdx.x == 0) {
        float v = warp_sums[0];
        #pragma unroll
        for (int w = 1; w < BDIM / 32; w++) v += warp_sums[w];
        // Pre-scaled fire-and-forget reduction straight into the output.
        // Result unused -> RED.E.ADD.F32: no return latency, CTA retires
        // immediately. d_out was zeroed by the memcpy node before this grid.
        atomicAdd(out, v * (1.0f / (float)Nc));
    }
}

extern "C" void kernel_launch(void* const* d_in, const int* in_sizes, int n_in,
                              void* d_out, int out_size)
{
    const float* img = (const float*)d_in[0];
    const int*   xA  = (const int*)d_in[1];
    const int*   yA  = (const int*)d_in[2];
    const int*   xB  = (const int*)d_in[3];
    const int*   yB  = (const int*)d_in[4];
    const int*   ord = (const int*)d_in[5];
    float* out = (float*)d_out;

    // Zero-init the (poisoned) output via a cheap D2D memcpy node, ordered
    // before the grid on the same stream. Device-to-device async memcpy is
    // explicitly graph-capture-legal per the harness rules.
    void* zero_addr = nullptr;
    cudaGetSymbolAddress(&zero_addr, g_zero);
    cudaMemcpyAsync(out, zero_addr, sizeof(float), cudaMemcpyDeviceToDevice, 0);

    loss_kernel<<<NBLK, BDIM>>>(img, xA, yA, xB, yB, ord, out);
}

// round 10
// speedup vs baseline: 1.0395x; 1.0010x over previous
#include <cuda_runtime.h>
#include <cstdint>

constexpr int Bc = 32;
constexpr int Hc = 512;
constexpr int Wc = 512;
constexpr int Pc = 100000;
constexpr long long Nc = (long long)Bc * Pc;   // 3,200,000 points
constexpr int BDIM = 256;
constexpr int PPT  = 4;                        // points per thread
constexpr int NBLK = (int)(Nc / ((long long)BDIM * PPT));  // 3125 blocks
static_assert(Nc % ((long long)BDIM * PPT) == 0, "grid must tile exactly");
static_assert(Pc % PPT == 0, "4 consecutive points always share a batch index");

__device__ float g_zero = 0.0f;   // source for the zero-init memcpy node

__device__ __forceinline__ float point_loss(float zA, float zB, int o) {
    float d  = zA - zB;
    float gt = (float)o - 1.0f;          // in {-1, 0, +1}
    float sm = log1pf(expf(-gt * d));    // soft-margin branch (gt = +/-1)
    return (o == 1) ? (d * d) : sm;
}

__device__ __forceinline__ int4 ldcs4(const int* p) {
    return __ldcs(reinterpret_cast<const int4*>(p));
}

// evict_last access policy (built once per thread, ~2 ALU ops)
__device__ __forceinline__ uint64_t make_evict_last_policy() {
    uint64_t pol;
    asm("createpolicy.fractional.L2::evict_last.b64 %0, 1.0;" : "=l"(pol));
    return pol;
}

// Image gather: non-coherent load with evict_last cache hint so the 33.5MB
// image stays L2-resident while the 64MB index stream (evict_first) passes.
__device__ __forceinline__ float ld_evict_last(const float* p, uint64_t pol) {
    float v;
    asm volatile("ld.global.nc.L2::cache_hint.f32 %0, [%1], %2;"
                 : "=f"(v) : "l"(p), "l"(pol));
    return v;
}

__global__ __launch_bounds__(BDIM)
void loss_kernel(const float* __restrict__ img,
                 const int* __restrict__ xA,
                 const int* __restrict__ yA,
                 const int* __restrict__ xB,
                 const int* __restrict__ yB,
                 const int* __restrict__ ord,
                 float* __restrict__ out)
{
    const long long base = ((long long)blockIdx.x * BDIM + threadIdx.x) * PPT;

    // 4 consecutive points: same batch (P % 4 == 0, base % 4 == 0)
    const int b = (int)(base / Pc);
    const float* __restrict__ imgb = img + (long long)b * (Hc * Wc);

    // 128-bit evict-first streaming loads of all five int32 streams
    int4 xa = ldcs4(xA + base);
    int4 ya = ldcs4(yA + base);
    int4 xb = ldcs4(xB + base);
    int4 yb = ldcs4(yB + base);
    int4 o4 = ldcs4(ord + base);

    // Offsets: y*512 + x
    unsigned offA0 = ((unsigned)ya.x << 9) | (unsigned)xa.x;
    unsigned offA1 = ((unsigned)ya.y << 9) | (unsigned)xa.y;
    unsigned offA2 = ((unsigned)ya.z << 9) | (unsigned)xa.z;
    unsigned offA3 = ((unsigned)ya.w << 9) | (unsigned)xa.w;
    unsigned offB0 = ((unsigned)yb.x << 9) | (unsigned)xb.x;
    unsigned offB1 = ((unsigned)yb.y << 9) | (unsigned)xb.y;
    unsigned offB2 = ((unsigned)yb.z << 9) | (unsigned)xb.z;
    unsigned offB3 = ((unsigned)yb.w << 9) | (unsigned)xb.w;

    const uint64_t pol = make_evict_last_policy();

    // Issue all 8 gathers before consuming (MLP)
    float zA0 = ld_evict_last(imgb + offA0, pol);
    float zA1 = ld_evict_last(imgb + offA1, pol);
    float zA2 = ld_evict_last(imgb + offA2, pol);
    float zA3 = ld_evict_last(imgb + offA3, pol);
    float zB0 = ld_evict_last(imgb + offB0, pol);
    float zB1 = ld_evict_last(imgb + offB1, pol);
    float zB2 = ld_evict_last(imgb + offB2, pol);
    float zB3 = ld_evict_last(imgb + offB3, pol);

    float s = point_loss(zA0, zB0, o4.x)
            + point_loss(zA1, zB1, o4.y)
            + point_loss(zA2, zB2, o4.z)
            + point_loss(zA3, zB3, o4.w);

    // Warp reduce
    #pragma unroll
    for (int off = 16; off > 0; off >>= 1)
        s += __shfl_xor_sync(0xFFFFFFFFu, s, off);

    __shared__ float warp_sums[BDIM / 32];
    int lane = threadIdx.x & 31;
    int wid  = threadIdx.x >> 5;
    if (lane == 0) warp_sums[wid] = s;
    __syncthreads();

    if (threadIdx.x == 0) {
        float v = warp_sums[0];
        #pragma unroll
        for (int w = 1; w < BDIM / 32; w++) v += warp_sums[w];
        // Pre-scaled fire-and-forget reduction straight into the output.
        atomicAdd(out, v * (1.0f / (float)Nc));
    }
}

extern "C" void kernel_launch(void* const* d_in, const int* in_sizes, int n_in,
                              void* d_out, int out_size)
{
    const float* img = (const float*)d_in[0];
    const int*   xA  = (const int*)d_in[1];
    const int*   yA  = (const int*)d_in[2];
    const int*   xB  = (const int*)d_in[3];
    const int*   yB  = (const int*)d_in[4];
    const int*   ord = (const int*)d_in[5];
    float* out = (float*)d_out;

    // Zero-init the (poisoned) output via a cheap D2D memcpy node.
    void* zero_addr = nullptr;
    cudaGetSymbolAddress(&zero_addr, g_zero);
    cudaMemcpyAsync(out, zero_addr, sizeof(float), cudaMemcpyDeviceToDevice, 0);

    loss_kernel<<<NBLK, BDIM>>>(img, xA, yA, xB, yB, ord, out);
}

// round 11
// speedup vs baseline: 1.0964x; 1.0548x over previous
#include <cuda_runtime.h>
#include <cstdint>

constexpr int Bc = 32;
constexpr int Hc = 512;
constexpr int Wc = 512;
constexpr int Pc = 100000;
constexpr long long Nc = (long long)Bc * Pc;   // 3,200,000 points
constexpr int BDIM  = 256;
constexpr int PPT   = 4;                       // points per chunk
constexpr int GRID  = 148 * 8;                 // persistent: one wave on 148 SMs
constexpr int NCHUNK = (int)(Nc / PPT);        // 800,000 chunks
static_assert(Nc % PPT == 0, "chunks tile exactly");
static_assert(Pc % PPT == 0, "4 consecutive points always share a batch index");

__device__ float g_zero = 0.0f;   // source for the zero-init memcpy node

__device__ __forceinline__ float point_loss(float zA, float zB, int o) {
    float d  = zA - zB;
    float gt = (float)o - 1.0f;          // in {-1, 0, +1}
    float sm = log1pf(expf(-gt * d));    // soft-margin branch (gt = +/-1)
    return (o == 1) ? (d * d) : sm;
}

__device__ __forceinline__ int4 ldcs4(const int* p) {
    return __ldcs(reinterpret_cast<const int4*>(p));
}

__global__ __launch_bounds__(BDIM)
void loss_kernel(const float* __restrict__ img,
                 const int* __restrict__ xA,
                 const int* __restrict__ yA,
                 const int* __restrict__ xB,
                 const int* __restrict__ yB,
                 const int* __restrict__ ord,
                 float* __restrict__ out)
{
    const int gtid   = blockIdx.x * BDIM + threadIdx.x;
    const int stride = GRID * BDIM;

    float acc = 0.0f;

    for (int c = gtid; c < NCHUNK; c += stride) {
        const long long base = (long long)c * PPT;
        const int b = (int)(base / Pc);
        const float* __restrict__ imgb = img + (long long)b * (Hc * Wc);

        // 128-bit evict-first streaming loads of all five int32 streams
        int4 xa = ldcs4(xA + base);
        int4 ya = ldcs4(yA + base);
        int4 xb = ldcs4(xB + base);
        int4 yb = ldcs4(yB + base);
        int4 o4 = ldcs4(ord + base);

        // Offsets: y*512 + x
        unsigned offA0 = ((unsigned)ya.x << 9) | (unsigned)xa.x;
        unsigned offA1 = ((unsigned)ya.y << 9) | (unsigned)xa.y;
        unsigned offA2 = ((unsigned)ya.z << 9) | (unsigned)xa.z;
        unsigned offA3 = ((unsigned)ya.w << 9) | (unsigned)xa.w;
        unsigned offB0 = ((unsigned)yb.x << 9) | (unsigned)xb.x;
        unsigned offB1 = ((unsigned)yb.y << 9) | (unsigned)xb.y;
        unsigned offB2 = ((unsigned)yb.z << 9) | (unsigned)xb.z;
        unsigned offB3 = ((unsigned)yb.w << 9) | (unsigned)xb.w;

        // Issue all 8 gathers before consuming (MLP)
        float zA0 = __ldg(imgb + offA0);
        float zA1 = __ldg(imgb + offA1);
        float zA2 = __ldg(imgb + offA2);
        float zA3 = __ldg(imgb + offA3);
        float zB0 = __ldg(imgb + offB0);
        float zB1 = __ldg(imgb + offB1);
        float zB2 = __ldg(imgb + offB2);
        float zB3 = __ldg(imgb + offB3);

        acc += point_loss(zA0, zB0, o4.x)
             + point_loss(zA1, zB1, o4.y)
             + point_loss(zA2, zB2, o4.z)
             + point_loss(zA3, zB3, o4.w);
    }

    // Warp reduce
    #pragma unroll
    for (int off = 16; off > 0; off >>= 1)
        acc += __shfl_xor_sync(0xFFFFFFFFu, acc, off);

    __shared__ float warp_sums[BDIM / 32];
    int lane = threadIdx.x & 31;
    int wid  = threadIdx.x >> 5;
    if (lane == 0) warp_sums[wid] = acc;
    __syncthreads();

    if (threadIdx.x == 0) {
        float v = warp_sums[0];
        #pragma unroll
        for (int w = 1; w < BDIM / 32; w++) v += warp_sums[w];
        // Pre-scaled fire-and-forget reduction straight into the output.
        atomicAdd(out, v * (1.0f / (float)Nc));
    }
}

extern "C" void kernel_launch(void* const* d_in, const int* in_sizes, int n_in,
                              void* d_out, int out_size)
{
    const float* img = (const float*)d_in[0];
    const int*   xA  = (const int*)d_in[1];
    const int*   yA  = (const int*)d_in[2];
    const int*   xB  = (const int*)d_in[3];
    const int*   yB  = (const int*)d_in[4];
    const int*   ord = (const int*)d_in[5];
    float* out = (float*)d_out;

    // Zero-init the (poisoned) output via a cheap D2D memcpy node.
    void* zero_addr = nullptr;
    cudaGetSymbolAddress(&zero_addr, g_zero);
    cudaMemcpyAsync(out, zero_addr, sizeof(float), cudaMemcpyDeviceToDevice, 0);

    loss_kernel<<<GRID, BDIM>>>(img, xA, yA, xB, yB, ord, out);
}

// round 12
// speedup vs baseline: 1.1066x; 1.0092x over previous
#include <cuda_runtime.h>
#include <cstdint>

constexpr int Bc = 32;
constexpr int Hc = 512;
constexpr int Wc = 512;
constexpr int Pc = 100000;
constexpr long long Nc = (long long)Bc * Pc;   // 3,200,000 points
constexpr int BDIM   = 256;
constexpr int PPT    = 4;                      // points per chunk
constexpr int GRID   = 148 * 4;                // persistent, one wave at 4 CTAs/SM
constexpr int NCHUNK = (int)(Nc / PPT);        // 800,000 chunks
static_assert(Nc % PPT == 0, "chunks tile exactly");
static_assert(Pc % PPT == 0, "4 consecutive points always share a batch index");

__device__ float g_zero = 0.0f;   // source for the zero-init memcpy node

__device__ __forceinline__ float point_loss(float zA, float zB, int o) {
    float d  = zA - zB;
    float gt = (float)o - 1.0f;          // in {-1, 0, +1}
    float sm = log1pf(expf(-gt * d));    // soft-margin branch (gt = +/-1)
    return (o == 1) ? (d * d) : sm;
}

__device__ __forceinline__ int4 ldcs4(const int* p) {
    return __ldcs(reinterpret_cast<const int4*>(p));
}

struct Chunk { int4 xa, ya, xb, yb, o4; };

__device__ __forceinline__ Chunk load_chunk(const int* xA, const int* yA,
                                            const int* xB, const int* yB,
                                            const int* ord, long long base) {
    Chunk c;
    c.xa = ldcs4(xA + base);
    c.ya = ldcs4(yA + base);
    c.xb = ldcs4(xB + base);
    c.yb = ldcs4(yB + base);
    c.o4 = ldcs4(ord + base);
    return c;
}

__global__ __launch_bounds__(BDIM)
void loss_kernel(const float* __restrict__ img,
                 const int* __restrict__ xA,
                 const int* __restrict__ yA,
                 const int* __restrict__ xB,
                 const int* __restrict__ yB,
                 const int* __restrict__ ord,
                 float* __restrict__ out)
{
    const int gtid   = blockIdx.x * BDIM + threadIdx.x;
    const int stride = GRID * BDIM;

    float acc = 0.0f;

    int c = gtid;
    Chunk cur;
    if (c < NCHUNK)
        cur = load_chunk(xA, yA, xB, yB, ord, (long long)c * PPT);

    while (c < NCHUNK) {
        const long long base = (long long)c * PPT;
        const int b = (int)(base / Pc);
        const float* __restrict__ imgb = img + (long long)b * (Hc * Wc);

        // Offsets: y*512 + x
        unsigned offA0 = ((unsigned)cur.ya.x << 9) | (unsigned)cur.xa.x;
        unsigned offA1 = ((unsigned)cur.ya.y << 9) | (unsigned)cur.xa.y;
        unsigned offA2 = ((unsigned)cur.ya.z << 9) | (unsigned)cur.xa.z;
        unsigned offA3 = ((unsigned)cur.ya.w << 9) | (unsigned)cur.xa.w;
        unsigned offB0 = ((unsigned)cur.yb.x << 9) | (unsigned)cur.xb.x;
        unsigned offB1 = ((unsigned)cur.yb.y << 9) | (unsigned)cur.xb.y;
        unsigned offB2 = ((unsigned)cur.yb.z << 9) | (unsigned)cur.xb.z;
        unsigned offB3 = ((unsigned)cur.yb.w << 9) | (unsigned)cur.xb.w;
        int4 o4 = cur.o4;

        // Issue all 8 gathers (current chunk)
        float zA0 = __ldg(imgb + offA0);
        float zA1 = __ldg(imgb + offA1);
        float zA2 = __ldg(imgb + offA2);
        float zA3 = __ldg(imgb + offA3);
        float zB0 = __ldg(imgb + offB0);
        float zB1 = __ldg(imgb + offB1);
        float zB2 = __ldg(imgb + offB2);
        float zB3 = __ldg(imgb + offB3);

        // Prefetch next chunk's indices — overlaps with the gathers above
        const int cn = c + stride;
        if (cn < NCHUNK)
            cur = load_chunk(xA, yA, xB, yB, ord, (long long)cn * PPT);

        acc += point_loss(zA0, zB0, o4.x)
             + point_loss(zA1, zB1, o4.y)
             + point_loss(zA2, zB2, o4.z)
             + point_loss(zA3, zB3, o4.w);

        c = cn;
    }

    // Warp reduce
    #pragma unroll
    for (int off = 16; off > 0; off >>= 1)
        acc += __shfl_xor_sync(0xFFFFFFFFu, acc, off);

    __shared__ float warp_sums[BDIM / 32];
    int lane = threadIdx.x & 31;
    int wid  = threadIdx.x >> 5;
    if (lane == 0) warp_sums[wid] = acc;
    __syncthreads();

    if (threadIdx.x == 0) {
        float v = warp_sums[0];
        #pragma unroll
        for (int w = 1; w < BDIM / 32; w++) v += warp_sums[w];
        // Pre-scaled fire-and-forget reduction straight into the output.
        atomicAdd(out, v * (1.0f / (float)Nc));
    }
}

extern "C" void kernel_launch(void* const* d_in, const int* in_sizes, int n_in,
                              void* d_out, int out_size)
{
    const float* img = (const float*)d_in[0];
    const int*   xA  = (const int*)d_in[1];
    const int*   yA  = (const int*)d_in[2];
    const int*   xB  = (const int*)d_in[3];
    const int*   yB  = (const int*)d_in[4];
    const int*   ord = (const int*)d_in[5];
    float* out = (float*)d_out;

    // Zero-init the (poisoned) output via a cheap D2D memcpy node.
    void* zero_addr = nullptr;
    cudaGetSymbolAddress(&zero_addr, g_zero);
    cudaMemcpyAsync(out, zero_addr, sizeof(float), cudaMemcpyDeviceToDevice, 0);

    loss_kernel<<<GRID, BDIM>>>(img, xA, yA, xB, yB, ord, out);
}